// round 1
// baseline (speedup 1.0000x reference)
#include <cuda_runtime.h>
#include <math.h>

// Problem constants (fixed by the dataset)
#define NN 50000
#define EE 800000
#define IN_F 92
#define ED_F 50
#define HH 64
#define LL 4
#define GG 512
#define BN_EPS 1e-5f

// ---------------- scratch (device globals; no allocations allowed) ----------
__device__ float  g_x[NN * HH];        // node features (current layer)
__device__ float  g_ea[EE * HH];       // edge embeddings (fixed after embed)
__device__ float  g_xproj[NN * 256];   // per-layer node projections [sm_d|sm_s|cv_d|cv_s]
__device__ float  g_agg[NN * HH];      // per-layer aggregated messages
__device__ double g_stats[128];        // BN sums: [0:64) sum, [64:128) sumsq
__device__ float  g_y[NN * HH];        // pre-pool features
__device__ float  g_pool[GG * HH];     // pooled sums
__device__ float  g_cnt[GG];           // per-graph node counts

// ---------------- helpers ----------------------------------------------------
__device__ __forceinline__ float softplus_f(float x) {
    // numerically stable: max(x,0) + log1p(exp(-|x|))  (matches jax.nn.softplus)
    return fmaxf(x, 0.f) + log1pf(__expf(-fabsf(x)));
}
__device__ __forceinline__ float sigmoid_f(float x) {
    return __fdividef(1.f, 1.f + __expf(-x));
}

// ---------------- generic [rows,K]@[K,64] + bias + relu ----------------------
// Used for: pre-node embed (K=92), pre-edge embed (K=50), pre-pool (K=64).
template <int K, int KP>
__global__ __launch_bounds__(256) void embed_kernel(
    const float* __restrict__ A, const float* __restrict__ W,
    const float* __restrict__ bias, float* __restrict__ out, int nrows)
{
    __shared__ float As[64 * KP];
    __shared__ float Bs[K * 64];
    const int r0 = blockIdx.x * 64;
    const int tid = threadIdx.x;

    for (int i = tid; i < 64 * K; i += 256) {
        int r = i / K, k = i - r * K;
        int gr = r0 + r;
        As[r * KP + k] = (gr < nrows) ? A[(size_t)gr * K + k] : 0.f;
    }
    for (int i = tid; i < K * 64; i += 256) Bs[i] = W[i];
    __syncthreads();

    const int rx = tid >> 4;   // 16 row groups x 4 rows
    const int cx = tid & 15;   // 16 col groups x 4 cols
    float acc[4][4];
#pragma unroll
    for (int i = 0; i < 4; i++)
#pragma unroll
        for (int j = 0; j < 4; j++) acc[i][j] = 0.f;

#pragma unroll 4
    for (int k = 0; k < K; k++) {
        float4 b = *(const float4*)&Bs[k * 64 + cx * 4];
#pragma unroll
        for (int i = 0; i < 4; i++) {
            float a = As[(rx * 4 + i) * KP + k];
            acc[i][0] += a * b.x; acc[i][1] += a * b.y;
            acc[i][2] += a * b.z; acc[i][3] += a * b.w;
        }
    }
    float4 bb = *(const float4*)&bias[cx * 4];
#pragma unroll
    for (int i = 0; i < 4; i++) {
        int gr = r0 + rx * 4 + i;
        if (gr < nrows) {
            float4 v;
            v.x = fmaxf(acc[i][0] + bb.x, 0.f);
            v.y = fmaxf(acc[i][1] + bb.y, 0.f);
            v.z = fmaxf(acc[i][2] + bb.z, 0.f);
            v.w = fmaxf(acc[i][3] + bb.w, 0.f);
            *(float4*)&out[(size_t)gr * 64 + cx * 4] = v;
        }
    }
}

// ---------------- per-layer node projections ---------------------------------
// xproj[n] = [ x@Wsm[0:64]+b_sm | x@Wsm[64:128] | x@Wcv[0:64]+b_cv | x@Wcv[64:128] ]
// blockIdx.y: 0 -> sm halves, 1 -> cv halves. C tile: 64 nodes x 128 cols.
__global__ __launch_bounds__(256) void node_proj_kernel(
    const float* __restrict__ smw, const float* __restrict__ cvw,
    const float* __restrict__ smb, const float* __restrict__ cvb, int l)
{
    __shared__ float As[64 * 64];
    __shared__ float Bs[64 * 128];
    const int r0 = blockIdx.x * 64;
    const int y = blockIdx.y;
    const int tid = threadIdx.x;
    const float* base = (y == 0 ? smw : cvw) + l * 192 * 64;

    for (int i = tid; i < 64 * 64; i += 256) {
        int gr = r0 + (i >> 6);
        As[i] = (gr < NN) ? g_x[r0 * 64 + i] : 0.f;
    }
    for (int i = tid; i < 64 * 128; i += 256) {
        int k = i >> 7, jj = i & 127;
        Bs[i] = base[(k + (jj & 64)) * 64 + (jj & 63)];
    }
    __syncthreads();

    const int rx = tid >> 4, cx = tid & 15;
    float accA[4][4], accB[4][4];
#pragma unroll
    for (int i = 0; i < 4; i++)
#pragma unroll
        for (int j = 0; j < 4; j++) { accA[i][j] = 0.f; accB[i][j] = 0.f; }

#pragma unroll 4
    for (int k = 0; k < 64; k++) {
        float4 bA = *(const float4*)&Bs[k * 128 + cx * 4];
        float4 bB = *(const float4*)&Bs[k * 128 + 64 + cx * 4];
#pragma unroll
        for (int i = 0; i < 4; i++) {
            float a = As[(rx * 4 + i) * 64 + k];
            accA[i][0] += a * bA.x; accA[i][1] += a * bA.y;
            accA[i][2] += a * bA.z; accA[i][3] += a * bA.w;
            accB[i][0] += a * bB.x; accB[i][1] += a * bB.y;
            accB[i][2] += a * bB.z; accB[i][3] += a * bB.w;
        }
    }
    const float* bias = (y == 0 ? smb : cvb) + l * 64;
    float4 bv = *(const float4*)&bias[cx * 4];
#pragma unroll
    for (int i = 0; i < 4; i++) {
        int n = r0 + rx * 4 + i;
        if (n < NN) {
            float4 vA, vB;
            vA.x = accA[i][0] + bv.x; vA.y = accA[i][1] + bv.y;
            vA.z = accA[i][2] + bv.z; vA.w = accA[i][3] + bv.w;
            vB.x = accB[i][0]; vB.y = accB[i][1];
            vB.z = accB[i][2]; vB.w = accB[i][3];
            *(float4*)&g_xproj[n * 256 + y * 128 + cx * 4] = vA;
            *(float4*)&g_xproj[n * 256 + y * 128 + 64 + cx * 4] = vB;
        }
    }
}

// ---------------- fused edge GEMM + gather + activation + scatter ------------
// For 64 edges: T = ea@[Wsm_e | Wcv_e] ([64e x 128]), then
// m = softplus(T_sm + proj_sm_d[dst] + proj_sm_s[src]) * sigmoid(T_cv + ...),
// atomic-added into g_agg[dst].
__global__ __launch_bounds__(256) void edge_conv_kernel(
    const float* __restrict__ smw, const float* __restrict__ cvw,
    const int* __restrict__ eidx, int l)
{
    __shared__ float As[64 * 64];
    __shared__ float Bs[64 * 128];
    const int e0 = blockIdx.x * 64;           // EE % 64 == 0, no guards needed
    const int tid = threadIdx.x;

    for (int i = tid; i < 64 * 64; i += 256) As[i] = g_ea[e0 * 64 + i];
    const float* sbase = smw + l * 12288 + 128 * 64;
    const float* cbase = cvw + l * 12288 + 128 * 64;
    for (int i = tid; i < 64 * 128; i += 256) {
        int k = i >> 7, jj = i & 127;
        const float* b = (jj < 64) ? sbase : cbase;
        Bs[i] = b[k * 64 + (jj & 63)];
    }
    __syncthreads();

    const int rx = tid >> 4, cx = tid & 15;
    float accS[4][4], accC[4][4];
#pragma unroll
    for (int i = 0; i < 4; i++)
#pragma unroll
        for (int j = 0; j < 4; j++) { accS[i][j] = 0.f; accC[i][j] = 0.f; }

#pragma unroll 4
    for (int k = 0; k < 64; k++) {
        float4 bS = *(const float4*)&Bs[k * 128 + cx * 4];
        float4 bC = *(const float4*)&Bs[k * 128 + 64 + cx * 4];
#pragma unroll
        for (int i = 0; i < 4; i++) {
            float a = As[(rx * 4 + i) * 64 + k];
            accS[i][0] += a * bS.x; accS[i][1] += a * bS.y;
            accS[i][2] += a * bS.z; accS[i][3] += a * bS.w;
            accC[i][0] += a * bC.x; accC[i][1] += a * bC.y;
            accC[i][2] += a * bC.z; accC[i][3] += a * bC.w;
        }
    }

#pragma unroll
    for (int i = 0; i < 4; i++) {
        int e = e0 + rx * 4 + i;
        int s = eidx[e];           // row 0 = src
        int d = eidx[EE + e];      // row 1 = dst
        const float4 gsd = *(const float4*)&g_xproj[d * 256 + cx * 4];
        const float4 gss = *(const float4*)&g_xproj[s * 256 + 64 + cx * 4];
        const float4 gcd = *(const float4*)&g_xproj[d * 256 + 128 + cx * 4];
        const float4 gcs = *(const float4*)&g_xproj[s * 256 + 192 + cx * 4];

        float sm0 = accS[i][0] + gsd.x + gss.x;
        float sm1 = accS[i][1] + gsd.y + gss.y;
        float sm2 = accS[i][2] + gsd.z + gss.z;
        float sm3 = accS[i][3] + gsd.w + gss.w;
        float cv0 = accC[i][0] + gcd.x + gcs.x;
        float cv1 = accC[i][1] + gcd.y + gcs.y;
        float cv2 = accC[i][2] + gcd.z + gcs.z;
        float cv3 = accC[i][3] + gcd.w + gcs.w;

        float* dstp = &g_agg[d * 64 + cx * 4];
        atomicAdd(dstp + 0, softplus_f(sm0) * sigmoid_f(cv0));
        atomicAdd(dstp + 1, softplus_f(sm1) * sigmoid_f(cv1));
        atomicAdd(dstp + 2, softplus_f(sm2) * sigmoid_f(cv2));
        atomicAdd(dstp + 3, softplus_f(sm3) * sigmoid_f(cv3));
    }
}

// ---------------- BN statistics ----------------------------------------------
__global__ __launch_bounds__(256) void bn_stats_kernel()
{
    const int tid = threadIdx.x;
    const int c = tid & 63;
    const int rl = tid >> 6;  // 0..3
    float s = 0.f, s2 = 0.f;
    for (int r = blockIdx.x * 4 + rl; r < NN; r += gridDim.x * 4) {
        float v = g_agg[r * 64 + c];
        s += v; s2 += v * v;
    }
    __shared__ float sh[512];
    sh[tid] = s; sh[256 + tid] = s2;
    __syncthreads();
    if (tid < 64) {
        float ts = sh[tid] + sh[tid + 64] + sh[tid + 128] + sh[tid + 192];
        float t2 = sh[256 + tid] + sh[256 + tid + 64] + sh[256 + tid + 128] + sh[256 + tid + 192];
        atomicAdd(&g_stats[tid], (double)ts);
        atomicAdd(&g_stats[64 + tid], (double)t2);
    }
}

// ---------------- BN apply + residual ----------------------------------------
__global__ __launch_bounds__(256) void bn_apply_kernel(
    const float* __restrict__ gamma, const float* __restrict__ beta, int l)
{
    int idx = blockIdx.x * 256 + threadIdx.x;
    if (idx >= NN * 64) return;
    int c = idx & 63;
    double mu = g_stats[c] * (1.0 / NN);
    double var = g_stats[64 + c] * (1.0 / NN) - mu * mu;
    float rstd = rsqrtf((float)var + BN_EPS);
    float h = (g_agg[idx] - (float)mu) * rstd * gamma[l * 64 + c] + beta[l * 64 + c];
    g_x[idx] = g_x[idx] + h;
}

// ---------------- zeroing ----------------------------------------------------
__global__ void zero_agg_kernel()
{
    int idx = blockIdx.x * 256 + threadIdx.x;
    if (idx < NN * 64) g_agg[idx] = 0.f;
    if (idx < 128) g_stats[idx] = 0.0;
}
__global__ void zero_pool_kernel()
{
    int idx = blockIdx.x * 256 + threadIdx.x;
    if (idx < GG * 64) g_pool[idx] = 0.f;
    if (idx < GG) g_cnt[idx] = 0.f;
}

// ---------------- global mean pool -------------------------------------------
__global__ __launch_bounds__(256) void pool_kernel(const int* __restrict__ batch)
{
    int idx = blockIdx.x * 256 + threadIdx.x;
    if (idx >= NN * 64) return;
    int r = idx >> 6, c = idx & 63;
    int g = batch[r];
    atomicAdd(&g_pool[g * 64 + c], g_y[idx]);
    if (c == 0) atomicAdd(&g_cnt[g], 1.f);
}

// ---------------- dense head -------------------------------------------------
__global__ __launch_bounds__(64) void head_kernel(
    const float* __restrict__ hw, const float* __restrict__ hb,
    const float* __restrict__ ow, const float* __restrict__ ob,
    float* __restrict__ out)
{
    __shared__ float v[64];
    __shared__ float red[64];
    const int g = blockIdx.x, c = threadIdx.x;
    v[c] = g_pool[g * 64 + c] / fmaxf(g_cnt[g], 1.f);
    __syncthreads();
#pragma unroll
    for (int j = 0; j < 2; j++) {
        float acc = hb[j * 64 + c];
        const float* W = hw + j * 4096;
#pragma unroll 8
        for (int k = 0; k < 64; k++) acc += v[k] * W[k * 64 + c];
        __syncthreads();
        v[c] = fmaxf(acc, 0.f);
        __syncthreads();
    }
    red[c] = v[c] * ow[c];
    __syncthreads();
    if (c < 32) {
        float t = red[c] + red[c + 32];
#pragma unroll
        for (int off = 16; off > 0; off >>= 1)
            t += __shfl_down_sync(0xffffffffu, t, off);
        if (c == 0) out[g] = t + ob[0];
    }
}

// ---------------- launch -----------------------------------------------------
extern "C" void kernel_launch(void* const* d_in, const int* in_sizes, int n_in,
                              void* d_out, int out_size)
{
    const float* x_in  = (const float*)d_in[0];
    const int*   eidx  = (const int*)  d_in[1];
    const float* eattr = (const float*)d_in[2];
    const int*   batch = (const int*)  d_in[3];
    const float* pnw = (const float*)d_in[4];
    const float* pnb = (const float*)d_in[5];
    const float* pew = (const float*)d_in[6];
    const float* peb = (const float*)d_in[7];
    const float* smw = (const float*)d_in[8];
    const float* smb = (const float*)d_in[9];
    const float* cvw = (const float*)d_in[10];
    const float* cvb = (const float*)d_in[11];
    const float* gam = (const float*)d_in[12];
    const float* bet = (const float*)d_in[13];
    const float* ppw = (const float*)d_in[14];
    const float* ppb = (const float*)d_in[15];
    const float* hw  = (const float*)d_in[16];
    const float* hb  = (const float*)d_in[17];
    const float* ow  = (const float*)d_in[18];
    const float* ob  = (const float*)d_in[19];
    float* out = (float*)d_out;

    float* p_x;  cudaGetSymbolAddress((void**)&p_x,  g_x);
    float* p_ea; cudaGetSymbolAddress((void**)&p_ea, g_ea);
    float* p_y;  cudaGetSymbolAddress((void**)&p_y,  g_y);

    const int NODE_BLOCKS = (NN + 63) / 64;   // 782
    const int EDGE_BLOCKS = EE / 64;          // 12500
    const int ELEM_BLOCKS = (NN * 64 + 255) / 256;

    // pre-conv embeds
    embed_kernel<IN_F, IN_F + 1><<<NODE_BLOCKS, 256>>>(x_in, pnw, pnb, p_x, NN);
    embed_kernel<ED_F, ED_F + 1><<<EDGE_BLOCKS, 256>>>(eattr, pew, peb, p_ea, EE);

    // message-passing layers
    for (int l = 0; l < LL; l++) {
        node_proj_kernel<<<dim3(NODE_BLOCKS, 2), 256>>>(smw, cvw, smb, cvb, l);
        zero_agg_kernel<<<ELEM_BLOCKS, 256>>>();
        edge_conv_kernel<<<EDGE_BLOCKS, 256>>>(smw, cvw, eidx, l);
        bn_stats_kernel<<<128, 256>>>();
        bn_apply_kernel<<<ELEM_BLOCKS, 256>>>(gam, bet, l);
    }

    // head
    embed_kernel<HH, HH + 1><<<NODE_BLOCKS, 256>>>(p_x, ppw, ppb, p_y, NN);
    zero_pool_kernel<<<(GG * 64 + 255) / 256, 256>>>();
    pool_kernel<<<ELEM_BLOCKS, 256>>>(batch);
    head_kernel<<<GG, 64>>>(hw, hb, ow, ob, out);
}

// round 3
// speedup vs baseline: 1.0565x; 1.0565x over previous
#include <cuda_runtime.h>
#include <cuda_bf16.h>
#include <math.h>

// Problem constants (fixed by the dataset)
#define NN 50000
#define EE 800000
#define IN_F 92
#define ED_F 50
#define HH 64
#define LL 4
#define GG 512
#define BN_EPS 1e-5f

// ---------------- scratch (device globals; no allocations allowed) ----------
__device__ float          g_x[NN * HH];       // node features (current layer)
__device__ __nv_bfloat16  g_ea_h[EE * HH];    // edge embed hi plane (bf16)
__device__ __nv_bfloat16  g_ea_l[EE * HH];    // edge embed lo plane (bf16)
__device__ __nv_bfloat16  g_wse_h[LL * 128 * 64]; // edge-weight hi planes [l][n][k]
__device__ __nv_bfloat16  g_wse_l[LL * 128 * 64]; // edge-weight lo planes
__device__ float          g_xproj[NN * 256];  // interleaved: [4j]=sm_d [4j+1]=cv_d [4j+2]=sm_s [4j+3]=cv_s
__device__ float          g_agg[NN * HH];     // per-layer aggregated messages
__device__ double         g_stats[128];       // BN sums: [0:64) sum, [64:128) sumsq
__device__ float          g_y[NN * HH];       // pre-pool features
__device__ float          g_pool[GG * HH];    // pooled sums
__device__ float          g_cnt[GG];          // per-graph node counts

// ---------------- helpers ----------------------------------------------------
__device__ __forceinline__ float softplus_f(float x) {
    return fmaxf(x, 0.f) + log1pf(__expf(-fabsf(x)));
}
__device__ __forceinline__ float sigmoid_f(float x) {
    return __fdividef(1.f, 1.f + __expf(-x));
}
__device__ __forceinline__ void split_bf16(float v, __nv_bfloat16& h, __nv_bfloat16& l) {
    h = __float2bfloat16(v);
    l = __float2bfloat16(v - __bfloat162float(h));
}
__device__ __forceinline__ void mma_bf16(float c[4], const unsigned a[4], const unsigned b[2]) {
    asm volatile(
        "mma.sync.aligned.m16n8k16.row.col.f32.bf16.bf16.f32 "
        "{%0,%1,%2,%3}, {%4,%5,%6,%7}, {%8,%9}, {%0,%1,%2,%3};"
        : "+f"(c[0]), "+f"(c[1]), "+f"(c[2]), "+f"(c[3])
        : "r"(a[0]), "r"(a[1]), "r"(a[2]), "r"(a[3]), "r"(b[0]), "r"(b[1]));
}

// ---------------- generic [rows,K]@[K,64] + bias + relu (fp32 out) -----------
template <int K, int KP>
__global__ __launch_bounds__(256) void embed_kernel(
    const float* __restrict__ A, const float* __restrict__ W,
    const float* __restrict__ bias, float* __restrict__ out, int nrows)
{
    __shared__ float As[64 * KP];
    __shared__ float Bs[K * 64];
    const int r0 = blockIdx.x * 64;
    const int tid = threadIdx.x;

    for (int i = tid; i < 64 * K; i += 256) {
        int r = i / K, k = i - r * K;
        int gr = r0 + r;
        As[r * KP + k] = (gr < nrows) ? A[(size_t)gr * K + k] : 0.f;
    }
    for (int i = tid; i < K * 64; i += 256) Bs[i] = W[i];
    __syncthreads();

    const int rx = tid >> 4, cx = tid & 15;
    float acc[4][4];
#pragma unroll
    for (int i = 0; i < 4; i++)
#pragma unroll
        for (int j = 0; j < 4; j++) acc[i][j] = 0.f;

#pragma unroll 4
    for (int k = 0; k < K; k++) {
        float4 b = *(const float4*)&Bs[k * 64 + cx * 4];
#pragma unroll
        for (int i = 0; i < 4; i++) {
            float a = As[(rx * 4 + i) * KP + k];
            acc[i][0] += a * b.x; acc[i][1] += a * b.y;
            acc[i][2] += a * b.z; acc[i][3] += a * b.w;
        }
    }
    float4 bb = *(const float4*)&bias[cx * 4];
#pragma unroll
    for (int i = 0; i < 4; i++) {
        int gr = r0 + rx * 4 + i;
        if (gr < nrows) {
            float4 v;
            v.x = fmaxf(acc[i][0] + bb.x, 0.f);
            v.y = fmaxf(acc[i][1] + bb.y, 0.f);
            v.z = fmaxf(acc[i][2] + bb.z, 0.f);
            v.w = fmaxf(acc[i][3] + bb.w, 0.f);
            *(float4*)&out[(size_t)gr * 64 + cx * 4] = v;
        }
    }
}

// ---------------- edge embed: [E,50]@[50,64]+bias+relu -> bf16 hi/lo planes --
__global__ __launch_bounds__(256) void embed_edge_kernel(
    const float* __restrict__ A, const float* __restrict__ W,
    const float* __restrict__ bias)
{
    const int K = ED_F, KP = ED_F + 1;
    __shared__ float As[64 * (ED_F + 1)];
    __shared__ float Bs[ED_F * 64];
    const int r0 = blockIdx.x * 64;
    const int tid = threadIdx.x;

    for (int i = tid; i < 64 * K; i += 256) {
        int r = i / K, k = i - r * K;
        As[r * KP + k] = A[(size_t)(r0 + r) * K + k];   // EE % 64 == 0
    }
    for (int i = tid; i < K * 64; i += 256) Bs[i] = W[i];
    __syncthreads();

    const int rx = tid >> 4, cx = tid & 15;
    float acc[4][4];
#pragma unroll
    for (int i = 0; i < 4; i++)
#pragma unroll
        for (int j = 0; j < 4; j++) acc[i][j] = 0.f;

#pragma unroll 2
    for (int k = 0; k < K; k++) {
        float4 b = *(const float4*)&Bs[k * 64 + cx * 4];
#pragma unroll
        for (int i = 0; i < 4; i++) {
            float a = As[(rx * 4 + i) * KP + k];
            acc[i][0] += a * b.x; acc[i][1] += a * b.y;
            acc[i][2] += a * b.z; acc[i][3] += a * b.w;
        }
    }
    float4 bb = *(const float4*)&bias[cx * 4];
#pragma unroll
    for (int i = 0; i < 4; i++) {
        int gr = r0 + rx * 4 + i;
        float v0 = fmaxf(acc[i][0] + bb.x, 0.f);
        float v1 = fmaxf(acc[i][1] + bb.y, 0.f);
        float v2 = fmaxf(acc[i][2] + bb.z, 0.f);
        float v3 = fmaxf(acc[i][3] + bb.w, 0.f);
        __nv_bfloat16 h0, l0, h1, l1, h2, l2, h3, l3;
        split_bf16(v0, h0, l0); split_bf16(v1, h1, l1);
        split_bf16(v2, h2, l2); split_bf16(v3, h3, l3);
        size_t base = (size_t)gr * 64 + cx * 4;
        *(__nv_bfloat162*)&g_ea_h[base]     = __halves2bfloat162(h0, h1);
        *(__nv_bfloat162*)&g_ea_h[base + 2] = __halves2bfloat162(h2, h3);
        *(__nv_bfloat162*)&g_ea_l[base]     = __halves2bfloat162(l0, l1);
        *(__nv_bfloat162*)&g_ea_l[base + 2] = __halves2bfloat162(l2, l3);
    }
}

// ---------------- edge-weight split planes (all layers, once) ----------------
// g_wse_*[l*8192 + n*64 + k]: n even -> smw col n/2, n odd -> cvw col n/2;
// k indexes rows 128..191 of the [192,64] weight.
__global__ void prep_wsplit_kernel(const float* __restrict__ smw,
                                   const float* __restrict__ cvw)
{
    int idx = blockIdx.x * 256 + threadIdx.x;
    if (idx >= LL * 8192) return;
    int l = idx >> 13, r = idx & 8191, n = r >> 6, k = r & 63;
    const float* w = (n & 1) ? cvw : smw;
    float v = w[l * 12288 + (128 + k) * 64 + (n >> 1)];
    __nv_bfloat16 h, lo;
    split_bf16(v, h, lo);
    g_wse_h[idx] = h;
    g_wse_l[idx] = lo;
}

// ---------------- per-layer node projections (interleaved output) ------------
// y=0: dst pairs (sm_d, cv_d) using W rows 0:64 (+ biases)
// y=1: src pairs (sm_s, cv_s) using W rows 64:128 (no bias)
// Physical col c in [0,128): even -> sm logical col c/2, odd -> cv col c/2.
// Thread (rx,cx) covers physical cols [cx*4 .. cx*4+3] AND [64+cx*4 .. 64+cx*4+3]
// -> logical j in {2cx, 2cx+1} and {32+2cx, 33+2cx}. Covers all j in [0,64).
__global__ __launch_bounds__(256) void node_proj_kernel(
    const float* __restrict__ smw, const float* __restrict__ cvw,
    const float* __restrict__ smb, const float* __restrict__ cvb, int l)
{
    __shared__ float As[64 * 64];
    __shared__ float Bs[64 * 128];
    const int r0 = blockIdx.x * 64;
    const int y = blockIdx.y;
    const int tid = threadIdx.x;

    for (int i = tid; i < 64 * 64; i += 256) {
        int gr = r0 + (i >> 6);
        As[i] = (gr < NN) ? g_x[(size_t)gr * 64 + (i & 63)] : 0.f;
    }
    for (int i = tid; i < 64 * 128; i += 256) {
        int k = i >> 7, c = i & 127;
        const float* w = (c & 1) ? cvw : smw;
        Bs[i] = w[l * 12288 + (y * 64 + k) * 64 + (c >> 1)];
    }
    __syncthreads();

    const int rx = tid >> 4, cx = tid & 15;
    float accA[4][4], accB[4][4];
#pragma unroll
    for (int i = 0; i < 4; i++)
#pragma unroll
        for (int j = 0; j < 4; j++) { accA[i][j] = 0.f; accB[i][j] = 0.f; }

#pragma unroll 4
    for (int k = 0; k < 64; k++) {
        float4 bA = *(const float4*)&Bs[k * 128 + cx * 4];
        float4 bB = *(const float4*)&Bs[k * 128 + 64 + cx * 4];
#pragma unroll
        for (int i = 0; i < 4; i++) {
            float a = As[(rx * 4 + i) * 64 + k];
            accA[i][0] += a * bA.x; accA[i][1] += a * bA.y;
            accA[i][2] += a * bA.z; accA[i][3] += a * bA.w;
            accB[i][0] += a * bB.x; accB[i][1] += a * bB.y;
            accB[i][2] += a * bB.z; accB[i][3] += a * bB.w;
        }
    }
    const int jA = 2 * cx;        // logical cols jA, jA+1   (physical 4cx..4cx+3)
    const int jB = 32 + 2 * cx;   // logical cols jB, jB+1   (physical 64+4cx..)
    float bA0 = 0.f, bA1 = 0.f, bA2 = 0.f, bA3 = 0.f;
    float bB0 = 0.f, bB1 = 0.f, bB2 = 0.f, bB3 = 0.f;
    if (y == 0) {
        bA0 = smb[l * 64 + jA];     bA1 = cvb[l * 64 + jA];
        bA2 = smb[l * 64 + jA + 1]; bA3 = cvb[l * 64 + jA + 1];
        bB0 = smb[l * 64 + jB];     bB1 = cvb[l * 64 + jB];
        bB2 = smb[l * 64 + jB + 1]; bB3 = cvb[l * 64 + jB + 1];
    }
#pragma unroll
    for (int i = 0; i < 4; i++) {
        int n = r0 + rx * 4 + i;
        if (n < NN) {
            *(float2*)&g_xproj[n * 256 + jA * 4 + y * 2] =
                make_float2(accA[i][0] + bA0, accA[i][1] + bA1);
            *(float2*)&g_xproj[n * 256 + (jA + 1) * 4 + y * 2] =
                make_float2(accA[i][2] + bA2, accA[i][3] + bA3);
            *(float2*)&g_xproj[n * 256 + jB * 4 + y * 2] =
                make_float2(accB[i][0] + bB0, accB[i][1] + bB1);
            *(float2*)&g_xproj[n * 256 + (jB + 1) * 4 + y * 2] =
                make_float2(accB[i][2] + bB2, accB[i][3] + bB3);
        }
    }
}

// ---------------- fused edge GEMM (bf16x3 tensor cores) + epilogue -----------
// Tile: 64 edges x 128 interleaved cols (S/C pairs), K=64.
// 8 warps = 2(M) x 4(N); warp tile 32x32 = 2 x m16 by 4 x n8; 4 k16 steps.
__global__ __launch_bounds__(256) void edge_conv_kernel(
    const int* __restrict__ eidx, int l)
{
    extern __shared__ __nv_bfloat16 smbuf[];
    __nv_bfloat16* Ah = smbuf;                 // [64][68]
    __nv_bfloat16* Al = Ah + 64 * 68;
    __nv_bfloat16* Bh = Al + 64 * 68;          // [128][68]
    __nv_bfloat16* Bl = Bh + 128 * 68;

    const int tid = threadIdx.x;
    const int e0 = blockIdx.x * 64;            // EE % 64 == 0

    for (int i = tid; i < 2048; i += 256) {
        int row = i >> 5, k2 = (i & 31) * 2;
        *(unsigned*)&Ah[row * 68 + k2] = *(const unsigned*)&g_ea_h[(size_t)(e0 + row) * 64 + k2];
        *(unsigned*)&Al[row * 68 + k2] = *(const unsigned*)&g_ea_l[(size_t)(e0 + row) * 64 + k2];
    }
    for (int i = tid; i < 4096; i += 256) {
        int n = i >> 5, k2 = (i & 31) * 2;
        *(unsigned*)&Bh[n * 68 + k2] = *(const unsigned*)&g_wse_h[l * 8192 + n * 64 + k2];
        *(unsigned*)&Bl[n * 68 + k2] = *(const unsigned*)&g_wse_l[l * 8192 + n * 64 + k2];
    }
    __syncthreads();

    const int lane = tid & 31, warp = tid >> 5;
    const int wm = warp >> 2, wn = warp & 3;
    const int g = lane >> 2, tg = lane & 3;

    float acc[2][4][4];
#pragma unroll
    for (int a = 0; a < 2; a++)
#pragma unroll
        for (int b = 0; b < 4; b++)
#pragma unroll
            for (int c = 0; c < 4; c++) acc[a][b][c] = 0.f;

#pragma unroll
    for (int ks = 0; ks < 4; ks++) {
        const int kb = ks * 16 + tg * 2;
        unsigned ah[2][4], alr[2][4], bh[4][2], blr[4][2];
#pragma unroll
        for (int mt = 0; mt < 2; mt++) {
            int r = wm * 32 + mt * 16 + g;
            ah[mt][0]  = *(const unsigned*)&Ah[r * 68 + kb];
            ah[mt][1]  = *(const unsigned*)&Ah[(r + 8) * 68 + kb];
            ah[mt][2]  = *(const unsigned*)&Ah[r * 68 + kb + 8];
            ah[mt][3]  = *(const unsigned*)&Ah[(r + 8) * 68 + kb + 8];
            alr[mt][0] = *(const unsigned*)&Al[r * 68 + kb];
            alr[mt][1] = *(const unsigned*)&Al[(r + 8) * 68 + kb];
            alr[mt][2] = *(const unsigned*)&Al[r * 68 + kb + 8];
            alr[mt][3] = *(const unsigned*)&Al[(r + 8) * 68 + kb + 8];
        }
#pragma unroll
        for (int nt = 0; nt < 4; nt++) {
            int n = wn * 32 + nt * 8 + g;
            bh[nt][0]  = *(const unsigned*)&Bh[n * 68 + kb];
            bh[nt][1]  = *(const unsigned*)&Bh[n * 68 + kb + 8];
            blr[nt][0] = *(const unsigned*)&Bl[n * 68 + kb];
            blr[nt][1] = *(const unsigned*)&Bl[n * 68 + kb + 8];
        }
#pragma unroll
        for (int mt = 0; mt < 2; mt++)
#pragma unroll
            for (int nt = 0; nt < 4; nt++) {
                mma_bf16(acc[mt][nt], ah[mt],  bh[nt]);
                mma_bf16(acc[mt][nt], ah[mt],  blr[nt]);
                mma_bf16(acc[mt][nt], alr[mt], bh[nt]);
            }
    }

    // epilogue: gather interleaved node projections, activate, scatter
#pragma unroll
    for (int mt = 0; mt < 2; mt++) {
        int e1 = e0 + wm * 32 + mt * 16 + g;
        int e2 = e1 + 8;
        int s1 = eidx[e1], d1 = eidx[EE + e1];
        int s2 = eidx[e2], d2 = eidx[EE + e2];
#pragma unroll
        for (int nt = 0; nt < 4; nt++) {
            int j = wn * 16 + nt * 4 + tg;
            float2 pd = *(const float2*)&g_xproj[d1 * 256 + 4 * j];
            float2 ps = *(const float2*)&g_xproj[s1 * 256 + 4 * j + 2];
            float m = softplus_f(acc[mt][nt][0] + pd.x + ps.x) *
                      sigmoid_f (acc[mt][nt][1] + pd.y + ps.y);
            atomicAdd(&g_agg[d1 * 64 + j], m);
            pd = *(const float2*)&g_xproj[d2 * 256 + 4 * j];
            ps = *(const float2*)&g_xproj[s2 * 256 + 4 * j + 2];
            m = softplus_f(acc[mt][nt][2] + pd.x + ps.x) *
                sigmoid_f (acc[mt][nt][3] + pd.y + ps.y);
            atomicAdd(&g_agg[d2 * 64 + j], m);
        }
    }
}

// ---------------- BN statistics ----------------------------------------------
__global__ __launch_bounds__(256) void bn_stats_kernel()
{
    const int tid = threadIdx.x;
    const int c = tid & 63;
    const int rl = tid >> 6;
    float s = 0.f, s2 = 0.f;
    for (int r = blockIdx.x * 4 + rl; r < NN; r += gridDim.x * 4) {
        float v = g_agg[r * 64 + c];
        s += v; s2 += v * v;
    }
    __shared__ float sh[512];
    sh[tid] = s; sh[256 + tid] = s2;
    __syncthreads();
    if (tid < 64) {
        float ts = sh[tid] + sh[tid + 64] + sh[tid + 128] + sh[tid + 192];
        float t2 = sh[256 + tid] + sh[256 + tid + 64] + sh[256 + tid + 128] + sh[256 + tid + 192];
        atomicAdd(&g_stats[tid], (double)ts);
        atomicAdd(&g_stats[64 + tid], (double)t2);
    }
}

// ---------------- BN apply + residual ----------------------------------------
__global__ __launch_bounds__(256) void bn_apply_kernel(
    const float* __restrict__ gamma, const float* __restrict__ beta, int l)
{
    int idx = blockIdx.x * 256 + threadIdx.x;
    if (idx >= NN * 64) return;
    int c = idx & 63;
    double mu = g_stats[c] * (1.0 / NN);
    double var = g_stats[64 + c] * (1.0 / NN) - mu * mu;
    float rstd = rsqrtf((float)var + BN_EPS);
    float h = (g_agg[idx] - (float)mu) * rstd * gamma[l * 64 + c] + beta[l * 64 + c];
    g_x[idx] = g_x[idx] + h;
}

// ---------------- zeroing ----------------------------------------------------
__global__ void zero_agg_kernel()
{
    int idx = blockIdx.x * 256 + threadIdx.x;
    if (idx < NN * 64) g_agg[idx] = 0.f;
    if (idx < 128) g_stats[idx] = 0.0;
}
__global__ void zero_pool_kernel()
{
    int idx = blockIdx.x * 256 + threadIdx.x;
    if (idx < GG * 64) g_pool[idx] = 0.f;
    if (idx < GG) g_cnt[idx] = 0.f;
}

// ---------------- global mean pool -------------------------------------------
__global__ __launch_bounds__(256) void pool_kernel(const int* __restrict__ batch)
{
    int idx = blockIdx.x * 256 + threadIdx.x;
    if (idx >= NN * 64) return;
    int r = idx >> 6, c = idx & 63;
    int g = batch[r];
    atomicAdd(&g_pool[g * 64 + c], g_y[idx]);
    if (c == 0) atomicAdd(&g_cnt[g], 1.f);
}

// ---------------- dense head -------------------------------------------------
__global__ __launch_bounds__(64) void head_kernel(
    const float* __restrict__ hw, const float* __restrict__ hb,
    const float* __restrict__ ow, const float* __restrict__ ob,
    float* __restrict__ out)
{
    __shared__ float v[64];
    __shared__ float red[64];
    const int g = blockIdx.x, c = threadIdx.x;
    v[c] = g_pool[g * 64 + c] / fmaxf(g_cnt[g], 1.f);
    __syncthreads();
#pragma unroll
    for (int j = 0; j < 2; j++) {
        float acc = hb[j * 64 + c];
        const float* W = hw + j * 4096;
#pragma unroll 8
        for (int k = 0; k < 64; k++) acc += v[k] * W[k * 64 + c];
        __syncthreads();
        v[c] = fmaxf(acc, 0.f);
        __syncthreads();
    }
    red[c] = v[c] * ow[c];
    __syncthreads();
    if (c < 32) {
        float t = red[c] + red[c + 32];
#pragma unroll
        for (int off = 16; off > 0; off >>= 1)
            t += __shfl_down_sync(0xffffffffu, t, off);
        if (c == 0) out[g] = t + ob[0];
    }
}

// ---------------- launch -----------------------------------------------------
extern "C" void kernel_launch(void* const* d_in, const int* in_sizes, int n_in,
                              void* d_out, int out_size)
{
    const float* x_in  = (const float*)d_in[0];
    const int*   eidx  = (const int*)  d_in[1];
    const float* eattr = (const float*)d_in[2];
    const int*   batch = (const int*)  d_in[3];
    const float* pnw = (const float*)d_in[4];
    const float* pnb = (const float*)d_in[5];
    const float* pew = (const float*)d_in[6];
    const float* peb = (const float*)d_in[7];
    const float* smw = (const float*)d_in[8];
    const float* smb = (const float*)d_in[9];
    const float* cvw = (const float*)d_in[10];
    const float* cvb = (const float*)d_in[11];
    const float* gam = (const float*)d_in[12];
    const float* bet = (const float*)d_in[13];
    const float* ppw = (const float*)d_in[14];
    const float* ppb = (const float*)d_in[15];
    const float* hw  = (const float*)d_in[16];
    const float* hb  = (const float*)d_in[17];
    const float* ow  = (const float*)d_in[18];
    const float* ob  = (const float*)d_in[19];
    float* out = (float*)d_out;

    float* p_x; cudaGetSymbolAddress((void**)&p_x, g_x);
    float* p_y; cudaGetSymbolAddress((void**)&p_y, g_y);

    const int NODE_BLOCKS = (NN + 63) / 64;   // 782
    const int EDGE_BLOCKS = EE / 64;          // 12500
    const int ELEM_BLOCKS = (NN * 64 + 255) / 256;
    const int EDGE_SMEM = (2 * 64 * 68 + 2 * 128 * 68) * (int)sizeof(__nv_bfloat16); // 52224

    // Idempotent, not a stream op — safe under graph capture; no static guard.
    cudaFuncSetAttribute(edge_conv_kernel,
                         cudaFuncAttributeMaxDynamicSharedMemorySize, EDGE_SMEM);

    // pre-conv embeds + weight split prep
    embed_kernel<IN_F, IN_F + 1><<<NODE_BLOCKS, 256>>>(x_in, pnw, pnb, p_x, NN);
    embed_edge_kernel<<<EDGE_BLOCKS, 256>>>(eattr, pew, peb);
    prep_wsplit_kernel<<<(LL * 8192 + 255) / 256, 256>>>(smw, cvw);

    // message-passing layers
    for (int l = 0; l < LL; l++) {
        node_proj_kernel<<<dim3(NODE_BLOCKS, 2), 256>>>(smw, cvw, smb, cvb, l);
        zero_agg_kernel<<<ELEM_BLOCKS, 256>>>();
        edge_conv_kernel<<<EDGE_BLOCKS, 256, EDGE_SMEM>>>(eidx, l);
        bn_stats_kernel<<<128, 256>>>();
        bn_apply_kernel<<<ELEM_BLOCKS, 256>>>(gam, bet, l);
    }

    // head
    embed_kernel<HH, HH + 1><<<NODE_BLOCKS, 256>>>(p_x, ppw, ppb, p_y, NN);
    zero_pool_kernel<<<(GG * 64 + 255) / 256, 256>>>();
    pool_kernel<<<ELEM_BLOCKS, 256>>>(batch);
    head_kernel<<<GG, 64>>>(hw, hb, ow, ob, out);
}